// round 15
// baseline (speedup 1.0000x reference)
#include <cuda_runtime.h>
#include <cuda_bf16.h>
#include <math.h>
#include <stdint.h>

#define NB 8
#define NT 2048
#define NE 1024
#define NH 64

// Projected Q (pre-scaled by 0.125), K, V as bf16 hi/lo, [B*T][H].
__device__ __nv_bfloat16 g_Qhi[NB * NT * NH];
__device__ __nv_bfloat16 g_Qlo[NB * NT * NH];
__device__ __nv_bfloat16 g_Khi[NB * NT * NH];
__device__ __nv_bfloat16 g_Klo[NB * NT * NH];
__device__ __nv_bfloat16 g_Vhi[NB * NT * NH];
__device__ __nv_bfloat16 g_Vlo[NB * NT * NH];
// W transposed+split to bf16 hi/lo, layout [m][h][e].
__device__ __nv_bfloat16 g_WThi[3 * NH * NE];
__device__ __nv_bfloat16 g_WTlo[3 * NH * NE];

__device__ __forceinline__ uint32_t s2u(const void* p) {
    uint32_t a;
    asm("{ .reg .u64 t; cvta.to.shared.u64 t, %1; cvt.u32.u64 %0, t; }"
        : "=r"(a) : "l"(p));
    return a;
}

__device__ __forceinline__ void split2(float v0, float v1, uint32_t& hi, uint32_t& lo) {
    __nv_bfloat16 h0 = __float2bfloat16(v0);
    __nv_bfloat16 h1 = __float2bfloat16(v1);
    __nv_bfloat162 hp = __halves2bfloat162(h0, h1);
    hi = *(uint32_t*)&hp;
    __nv_bfloat162 lp = __halves2bfloat162(
        __float2bfloat16(v0 - __bfloat162float(h0)),
        __float2bfloat16(v1 - __bfloat162float(h1)));
    lo = *(uint32_t*)&lp;
}

#define LDSM4(r, a)                                                            \
    asm volatile("ldmatrix.sync.aligned.m8n8.x4.shared.b16 {%0,%1,%2,%3}, [%4];" \
        : "=r"((r)[0]), "=r"((r)[1]), "=r"((r)[2]), "=r"((r)[3]) : "r"(a))

#define LDSM4T(r, a)                                                           \
    asm volatile("ldmatrix.sync.aligned.m8n8.x4.trans.shared.b16 {%0,%1,%2,%3}, [%4];" \
        : "=r"((r)[0]), "=r"((r)[1]), "=r"((r)[2]), "=r"((r)[3]) : "r"(a))

#define MMA16816(dd, a, b)                                                     \
    asm volatile("mma.sync.aligned.m16n8k16.row.col.f32.bf16.bf16.f32 "        \
        "{%0,%1,%2,%3}, {%4,%5,%6,%7}, {%8,%9}, {%0,%1,%2,%3};"                \
        : "+f"((dd)[0]), "+f"((dd)[1]), "+f"((dd)[2]), "+f"((dd)[3])           \
        : "r"((a)[0]), "r"((a)[1]), "r"((a)[2]), "r"((a)[3]),                  \
          "r"((b)[0]), "r"((b)[1]))

#define CP_ASYNC16(dst, src)                                                   \
    asm volatile("cp.async.cg.shared.global [%0], [%1], 16;"                   \
        :: "r"(dst), "l"(src))
#define CP_COMMIT() asm volatile("cp.async.commit_group;")
#define CP_WAIT(n)  asm volatile("cp.async.wait_group %0;" :: "n"(n))

// ---------------------------------------------------------------------------
// Kernel 0: W -> W^T hi/lo via smem transpose (coalesced 128B row writes).
// ---------------------------------------------------------------------------
__global__ __launch_bounds__(256) void wconv_kernel(
    const float* __restrict__ Wq, const float* __restrict__ Wk,
    const float* __restrict__ Wv)
{
    __shared__ float tile[64][65];
    const int m  = blockIdx.y;
    const int e0 = blockIdx.x * 64;
    const float* W = (m == 0) ? Wq : (m == 1 ? Wk : Wv);
    const int tid = threadIdx.x;

    #pragma unroll
    for (int it = 0; it < 4; ++it) {
        int e  = (tid >> 4) + it * 16;
        int h4 = (tid & 15) * 4;
        float4 v = *(const float4*)(W + (size_t)(e0 + e) * NH + h4);
        tile[h4 + 0][e] = v.x; tile[h4 + 1][e] = v.y;
        tile[h4 + 2][e] = v.z; tile[h4 + 3][e] = v.w;
    }
    __syncthreads();

    #pragma unroll
    for (int it = 0; it < 4; ++it) {
        int u   = tid + it * 256;
        int arr = u >> 9;
        int rem = u & 511;
        int h   = rem >> 3;
        int gp  = rem & 7;
        uint32_t pk[4];
        #pragma unroll
        for (int j = 0; j < 4; ++j) {
            float f0 = tile[h][gp * 8 + 2 * j];
            float f1 = tile[h][gp * 8 + 2 * j + 1];
            uint32_t hi, lo;
            split2(f0, f1, hi, lo);
            pk[j] = arr ? lo : hi;
        }
        __nv_bfloat16* dst = (arr ? g_WTlo : g_WThi) +
                             ((size_t)(m * NH + h) * NE + e0 + gp * 8);
        *(uint4*)dst = make_uint4(pk[0], pk[1], pk[2], pk[3]);
    }
}

// ---------------------------------------------------------------------------
// Kernel 1: fused QKV projection, mma.sync bf16 split-2, PIPELINED
// (byte-identical to the verified Round-12/14 version).
// ---------------------------------------------------------------------------
#define QSM_AHI 0
#define QSM_ALO 16384
#define QSM_B0  32768
#define QSM_B1  81920
#define QSM_BLO_OFF 24576
#define QSM_BYTES 131072

__global__ __launch_bounds__(512, 1) void qkv_mma_kernel(const float* __restrict__ x)
{
    extern __shared__ char smem[];
    const uint32_t sb = s2u(smem);
    const int tid  = threadIdx.x;
    const int lane = tid & 31;
    const int wid  = tid >> 5;
    const int wm   = wid & 3;
    const int wn   = wid >> 2;
    const int row0 = blockIdx.x * 128;

    float d[2][6][4] = {};

    const int xr = tid >> 2;
    const int xk = (tid & 3) * 16;

    int wsp[6], wrow[6], wq[6];
    uint32_t wdst[6];
    #pragma unroll
    for (int i = 0; i < 6; ++i) {
        int lin = tid + i * 512;
        wsp[i]  = (lin >= 1536) ? 1 : 0;
        int l2  = lin - wsp[i] * 1536;
        wrow[i] = l2 >> 3;
        wq[i]   = l2 & 7;
        wdst[i] = (uint32_t)(wsp[i] * QSM_BLO_OFF + wrow[i] * 128 +
                             ((wq[i] * 16) ^ ((wrow[i] & 7) << 4)));
    }

    float4 xrg[4];
    #pragma unroll
    for (int i = 0; i < 4; ++i)
        xrg[i] = *(const float4*)(x + (size_t)(row0 + xr) * NE + xk + i * 4);
    #pragma unroll
    for (int i = 0; i < 6; ++i) {
        const __nv_bfloat16* src =
            (wsp[i] ? g_WTlo : g_WThi) + ((size_t)wrow[i] * NE + wq[i] * 8);
        CP_ASYNC16(sb + QSM_B0 + wdst[i], src);
    }
    CP_COMMIT();

    #pragma unroll 1
    for (int c = 0; c < 16; ++c) {
        const uint32_t bbase = (c & 1) ? QSM_B1 : QSM_B0;
        __syncthreads();

        #pragma unroll
        for (int i = 0; i < 4; ++i) {
            int k = xk + i * 4;
            uint32_t hi01, lo01, hi23, lo23;
            split2(xrg[i].x, xrg[i].y, hi01, lo01);
            split2(xrg[i].z, xrg[i].w, hi23, lo23);
            uint32_t off = (uint32_t)(xr * 128) + (uint32_t)((k * 2) ^ ((xr & 7) << 4));
            *(uint2*)(smem + QSM_AHI + off) = make_uint2(hi01, hi23);
            *(uint2*)(smem + QSM_ALO + off) = make_uint2(lo01, lo23);
        }

        if (c < 15) {
            const int k0n = (c + 1) * 64;
            const uint32_t nb = (c & 1) ? QSM_B0 : QSM_B1;
            #pragma unroll
            for (int i = 0; i < 6; ++i) {
                const __nv_bfloat16* src =
                    (wsp[i] ? g_WTlo : g_WThi) +
                    ((size_t)wrow[i] * NE + k0n + wq[i] * 8);
                CP_ASYNC16(sb + nb + wdst[i], src);
            }
            CP_COMMIT();
            #pragma unroll
            for (int i = 0; i < 4; ++i)
                xrg[i] = *(const float4*)(x + (size_t)(row0 + xr) * NE + k0n + xk + i * 4);
            CP_WAIT(1);
        } else {
            CP_WAIT(0);
        }
        __syncthreads();

        #pragma unroll
        for (int ks = 0; ks < 4; ++ks) {
            const int kb = ks * 32;
            uint32_t aH[2][4], aL[2][4];
            {
                int lr  = lane & 15;
                int lkb = kb + ((lane >> 4) << 4);
                #pragma unroll
                for (int mf = 0; mf < 2; ++mf) {
                    int r = wm * 32 + mf * 16 + lr;
                    uint32_t a = sb + QSM_AHI + r * 128 + (lkb ^ ((r & 7) << 4));
                    LDSM4(aH[mf], a);
                    LDSM4(aL[mf], a + (QSM_ALO - QSM_AHI));
                }
            }
            uint32_t bH[3][4], bL[3][4];
            {
                int nro = (lane & 7) + ((lane >> 4) << 3);
                int lkb = kb + (((lane >> 3) & 1) << 4);
                #pragma unroll
                for (int p = 0; p < 3; ++p) {
                    int r = wn * 48 + p * 16 + nro;
                    uint32_t a = sb + bbase + r * 128 + (lkb ^ ((r & 7) << 4));
                    LDSM4(bH[p], a);
                    LDSM4(bL[p], a + QSM_BLO_OFF);
                }
            }
            #pragma unroll
            for (int mf = 0; mf < 2; ++mf) {
                #pragma unroll
                for (int nf = 0; nf < 6; ++nf) {
                    uint32_t* bh = &bH[nf >> 1][(nf & 1) * 2];
                    uint32_t* bl = &bL[nf >> 1][(nf & 1) * 2];
                    MMA16816(d[mf][nf], aH[mf], bh);
                    MMA16816(d[mf][nf], aH[mf], bl);
                    MMA16816(d[mf][nf], aL[mf], bh);
                }
            }
        }
    }

    const int g = lane >> 2, t = lane & 3;
    #pragma unroll
    for (int mf = 0; mf < 2; ++mf) {
        int r_lo = row0 + wm * 32 + mf * 16 + g;
        #pragma unroll
        for (int nf = 0; nf < 6; ++nf) {
            int col = wn * 48 + nf * 8 + 2 * t;
            int m = col >> 6, h = col & 63;
            float sc = (m == 0) ? 0.125f : 1.0f;
            __nv_bfloat16* Ohi = (m == 0) ? g_Qhi : (m == 1 ? g_Khi : g_Vhi);
            __nv_bfloat16* Olo = (m == 0) ? g_Qlo : (m == 1 ? g_Klo : g_Vlo);
            uint32_t hi, lo;
            split2(d[mf][nf][0] * sc, d[mf][nf][1] * sc, hi, lo);
            *(uint32_t*)(Ohi + (size_t)r_lo * NH + h) = hi;
            *(uint32_t*)(Olo + (size_t)r_lo * NH + h) = lo;
            split2(d[mf][nf][2] * sc, d[mf][nf][3] * sc, hi, lo);
            *(uint32_t*)(Ohi + (size_t)(r_lo + 8) * NH + h) = hi;
            *(uint32_t*)(Olo + (size_t)(r_lo + 8) * NH + h) = lo;
        }
    }
}

// ---------------------------------------------------------------------------
// Kernel 2: causal flash attention. Loop body identical to R14 (2-product S,
// no-max softmax, double-buffered KV, 1 barrier/tile). NEW: one q-tile per
// CTA, grid 256, smem 72.5KB, occupancy 2 CTAs/SM. Work pairing exploits
// bid%148 SM placement: bids b and b+148 co-reside, assigned complementary
// tile sizes (sum = 38 units); the 40 lone slots get the 40 smallest tiles.
// ---------------------------------------------------------------------------
#define ASM_QHI  0
#define ASM_KV0  8192
#define ASM_KV1  40960
#define ASM_REDL 73728
#define ASM_BYTES 74240
#define MASKV (-1e30f)

__global__ __launch_bounds__(256, 2) void attn_mma_kernel(float* __restrict__ out)
{
    extern __shared__ char sm[];
    const uint32_t sb = s2u(sm);
    float* REDl = (float*)(sm + ASM_REDL);

    const int tid  = threadIdx.x;
    const int lane = tid & 31;
    const int wid  = tid >> 5;
    const int wm   = wid & 3;     // m-slice (16 rows)
    const int ns   = wid >> 2;    // n-side (key cols 0..31 / 32..63)
    const int g    = lane >> 2;
    const int t    = lane & 3;

    // bid -> (qt, batch): complementary pairing across the bid%148 SM map.
    int bid = blockIdx.x;
    int qt, b;
    if (bid < 104)      { qt = 31 - (bid >> 3);      b = bid & 7; }
    else if (bid < 108) { qt = 18;                    b = (bid - 104) * 2; }
    else if (bid < 148) { int u = bid - 108; qt = u >> 3; b = u & 7; }
    else if (bid < 252) { int p = bid - 148; qt = 5 + (p >> 3); b = p & 7; }
    else                { qt = 18;                    b = (bid - 252) * 2 + 1; }

    const size_t boff = (size_t)b * NT * NH;
    const __nv_bfloat16* kvp[4] = {g_Khi + boff, g_Klo + boff,
                                   g_Vhi + boff, g_Vlo + boff};
    float* Ob = out + boff;
    const int row0 = qt * 64;

    // Q tile (hi only) -> smem: 512 uint4, 2 per thread.
    #pragma unroll
    for (int it = 0; it < 2; ++it) {
        int u = tid + it * 256;
        int r = u >> 3, gp = u & 7;
        const __nv_bfloat16* src =
            g_Qhi + boff + (size_t)(row0 + r) * NH + gp * 8;
        uint4 v = *(const uint4*)src;
        *(uint4*)(sm + ASM_QHI + r * 128 +
                  ((gp * 16) ^ ((r & 7) << 4))) = v;
    }

    float Of[8][4] = {};
    float lsum0 = 0.f, lsum1 = 0.f;

    // Tile 0 -> buf0.
    uint4 pf[8];
    #pragma unroll
    for (int it = 0; it < 8; ++it) {
        int u = tid + it * 256;
        int arr = u >> 9, rem = u & 511;
        int r = rem >> 3, gp = rem & 7;
        pf[it] = *(const uint4*)(kvp[arr] + (size_t)r * NH + gp * 8);
    }
    #pragma unroll
    for (int it = 0; it < 8; ++it) {
        int u = tid + it * 256;
        int arr = u >> 9, rem = u & 511;
        int r = rem >> 3, gp = rem & 7;
        *(uint4*)(sm + ASM_KV0 + arr * 8192 + r * 128 +
                  ((gp * 16) ^ ((r & 7) << 4))) = pf[it];
    }
    __syncthreads();  // Q + buf0 ready

    #pragma unroll 1
    for (int jt = 0; jt <= qt; ++jt) {
        const uint32_t ub = sb + ((jt & 1) ? ASM_KV1 : ASM_KV0);

        // Prefetch next tile (overlaps compute).
        if (jt < qt) {
            #pragma unroll
            for (int it = 0; it < 8; ++it) {
                int u = tid + it * 256;
                int arr = u >> 9, rem = u & 511;
                int r = rem >> 3, gp = rem & 7;
                pf[it] = *(const uint4*)(kvp[arr] +
                          (size_t)((jt + 1) * 64 + r) * NH + gp * 8);
            }
        }

        // ---- S = Q K^T (2 split products: qH*kH + qH*kL) ----
        float S[4][4] = {};
        #pragma unroll
        for (int kf = 0; kf < 4; ++kf) {
            const int kb = kf * 32;
            uint32_t aH[4];
            {
                int r = wm * 16 + (lane & 15);
                int lkb = kb + ((lane >> 4) << 4);
                uint32_t a = sb + ASM_QHI + r * 128 + (lkb ^ ((r & 7) << 4));
                LDSM4(aH, a);
            }
            uint32_t bKH[2][4], bKL[2][4];
            {
                int nro = (lane & 7) + ((lane >> 4) << 3);
                int lkb = kb + (((lane >> 3) & 1) << 4);
                #pragma unroll
                for (int p = 0; p < 2; ++p) {
                    int r = ns * 32 + p * 16 + nro;
                    uint32_t a = ub + r * 128 + (lkb ^ ((r & 7) << 4));
                    LDSM4(bKH[p], a);
                    LDSM4(bKL[p], a + 8192);
                }
            }
            #pragma unroll
            for (int nf = 0; nf < 4; ++nf) {
                uint32_t* bh = &bKH[nf >> 1][(nf & 1) * 2];
                uint32_t* bl = &bKL[nf >> 1][(nf & 1) * 2];
                MMA16816(S[nf], aH, bh);
                MMA16816(S[nf], aH, bl);
            }
        }

        // ---- mask (diag tile only) + exp (shift-0 softmax) ----
        if (jt == qt) {
            #pragma unroll
            for (int nf = 0; nf < 4; ++nf) {
                int col = ns * 32 + nf * 8 + 2 * t;
                int r0r = wm * 16 + g;
                if (col     > r0r)     S[nf][0] = MASKV;
                if (col + 1 > r0r)     S[nf][1] = MASKV;
                if (col     > r0r + 8) S[nf][2] = MASKV;
                if (col + 1 > r0r + 8) S[nf][3] = MASKV;
            }
        }
        #pragma unroll
        for (int nf = 0; nf < 4; ++nf) {
            S[nf][0] = __expf(S[nf][0]); lsum0 += S[nf][0];
            S[nf][1] = __expf(S[nf][1]); lsum0 += S[nf][1];
            S[nf][2] = __expf(S[nf][2]); lsum1 += S[nf][2];
            S[nf][3] = __expf(S[nf][3]); lsum1 += S[nf][3];
        }

        // ---- pack P into A-fragments (register-only) ----
        uint32_t pH[2][4], pL[2][4];
        #pragma unroll
        for (int kk = 0; kk < 2; ++kk) {
            split2(S[2 * kk][0],     S[2 * kk][1],     pH[kk][0], pL[kk][0]);
            split2(S[2 * kk][2],     S[2 * kk][3],     pH[kk][1], pL[kk][1]);
            split2(S[2 * kk + 1][0], S[2 * kk + 1][1], pH[kk][2], pL[kk][2]);
            split2(S[2 * kk + 1][2], S[2 * kk + 1][3], pH[kk][3], pL[kk][3]);
        }

        // ---- O += P V over this warp's 32 keys ----
        #pragma unroll
        for (int kk = 0; kk < 2; ++kk) {
            int jrow = ns * 32 + kk * 16 + (lane & 7) + ((lane >> 3) & 1) * 8;
            #pragma unroll
            for (int hp = 0; hp < 4; ++hp) {
                int hbyte = hp * 32 + ((lane >> 4) << 4);
                uint32_t a = ub + 16384 + jrow * 128 +
                             (hbyte ^ ((jrow & 7) << 4));
                uint32_t vH[4], vL[4];
                LDSM4T(vH, a);
                LDSM4T(vL, a + 8192);
                #pragma unroll
                for (int e = 0; e < 2; ++e) {
                    int hf = 2 * hp + e;
                    uint32_t* bh = &vH[e * 2];
                    uint32_t* bl = &vL[e * 2];
                    MMA16816(Of[hf], pH[kk], bh);
                    MMA16816(Of[hf], pH[kk], bl);
                    MMA16816(Of[hf], pL[kk], bh);
                }
            }
        }

        // ---- publish next tile (single barrier per iteration) ----
        if (jt < qt) {
            char* nb = sm + ((jt & 1) ? ASM_KV0 : ASM_KV1);
            #pragma unroll
            for (int it = 0; it < 8; ++it) {
                int u = tid + it * 256;
                int arr = u >> 9, rem = u & 511;
                int r = rem >> 3, gp = rem & 7;
                *(uint4*)(nb + arr * 8192 + r * 128 +
                          ((gp * 16) ^ ((r & 7) << 4))) = pf[it];
            }
            __syncthreads();
        }
    }

    // ---- reduce l within quad ----
    lsum0 += __shfl_xor_sync(0xffffffffu, lsum0, 1);
    lsum0 += __shfl_xor_sync(0xffffffffu, lsum0, 2);
    lsum1 += __shfl_xor_sync(0xffffffffu, lsum1, 1);
    lsum1 += __shfl_xor_sync(0xffffffffu, lsum1, 2);

    // ---- merge the two n-side accumulators, normalize, store ----
    __syncthreads();  // all compute (incl. reads of KV0) done
    if (ns == 1) {
        float* Oex = (float*)(sm + ASM_KV0);
        #pragma unroll
        for (int hf = 0; hf < 8; ++hf)
            *(float4*)&Oex[((wm * 32 + lane) * 32) + hf * 4] =
                make_float4(Of[hf][0], Of[hf][1], Of[hf][2], Of[hf][3]);
        if (t == 0) {
            REDl[wm * 16 + g]     = lsum0;
            REDl[wm * 16 + 8 + g] = lsum1;
        }
    }
    __syncthreads();
    if (ns == 0) {
        const float* Oex = (const float*)(sm + ASM_KV0);
        float lt0 = lsum0 + REDl[wm * 16 + g];
        float lt1 = lsum1 + REDl[wm * 16 + 8 + g];
        float inv0 = 1.0f / lt0;
        float inv1 = 1.0f / lt1;
        int r_g = row0 + wm * 16 + g;
        #pragma unroll
        for (int hf = 0; hf < 8; ++hf) {
            float4 ox = *(const float4*)&Oex[((wm * 32 + lane) * 32) + hf * 4];
            int h = hf * 8 + 2 * t;
            *(float2*)(Ob + (size_t)r_g * NH + h) =
                make_float2((Of[hf][0] + ox.x) * inv0, (Of[hf][1] + ox.y) * inv0);
            *(float2*)(Ob + (size_t)(r_g + 8) * NH + h) =
                make_float2((Of[hf][2] + ox.z) * inv1, (Of[hf][3] + ox.w) * inv1);
        }
    }
}

extern "C" void kernel_launch(void* const* d_in, const int* in_sizes, int n_in,
                              void* d_out, int out_size)
{
    const float* x  = (const float*)d_in[0];
    const float* Wq = (const float*)d_in[1];
    const float* Wk = (const float*)d_in[2];
    const float* Wv = (const float*)d_in[3];
    float* out = (float*)d_out;

    (void)cudaFuncSetAttribute(qkv_mma_kernel,
                               cudaFuncAttributeMaxDynamicSharedMemorySize, QSM_BYTES);
    (void)cudaFuncSetAttribute(attn_mma_kernel,
                               cudaFuncAttributeMaxDynamicSharedMemorySize, ASM_BYTES);

    wconv_kernel<<<dim3(16, 3), 256>>>(Wq, Wk, Wv);
    qkv_mma_kernel<<<128, 512, QSM_BYTES>>>(x);
    attn_mma_kernel<<<256, 256, ASM_BYTES>>>(out);
}

// round 17
// speedup vs baseline: 1.0942x; 1.0942x over previous
#include <cuda_runtime.h>
#include <cuda_bf16.h>
#include <math.h>
#include <stdint.h>

#define NB 8
#define NT 2048
#define NE 1024
#define NH 64

// Projected Q (pre-scaled by 0.125), K, V as bf16 hi/lo, [B*T][H].
__device__ __nv_bfloat16 g_Qhi[NB * NT * NH];
__device__ __nv_bfloat16 g_Qlo[NB * NT * NH];
__device__ __nv_bfloat16 g_Khi[NB * NT * NH];
__device__ __nv_bfloat16 g_Klo[NB * NT * NH];
__device__ __nv_bfloat16 g_Vhi[NB * NT * NH];
__device__ __nv_bfloat16 g_Vlo[NB * NT * NH];
// W transposed+split to bf16 hi/lo, layout [m][h][e].
__device__ __nv_bfloat16 g_WThi[3 * NH * NE];
__device__ __nv_bfloat16 g_WTlo[3 * NH * NE];

__device__ __forceinline__ uint32_t s2u(const void* p) {
    uint32_t a;
    asm("{ .reg .u64 t; cvta.to.shared.u64 t, %1; cvt.u32.u64 %0, t; }"
        : "=r"(a) : "l"(p));
    return a;
}

__device__ __forceinline__ void split2(float v0, float v1, uint32_t& hi, uint32_t& lo) {
    __nv_bfloat16 h0 = __float2bfloat16(v0);
    __nv_bfloat16 h1 = __float2bfloat16(v1);
    __nv_bfloat162 hp = __halves2bfloat162(h0, h1);
    hi = *(uint32_t*)&hp;
    __nv_bfloat162 lp = __halves2bfloat162(
        __float2bfloat16(v0 - __bfloat162float(h0)),
        __float2bfloat16(v1 - __bfloat162float(h1)));
    lo = *(uint32_t*)&lp;
}

#define LDSM4(r, a)                                                            \
    asm volatile("ldmatrix.sync.aligned.m8n8.x4.shared.b16 {%0,%1,%2,%3}, [%4];" \
        : "=r"((r)[0]), "=r"((r)[1]), "=r"((r)[2]), "=r"((r)[3]) : "r"(a))

#define LDSM4T(r, a)                                                           \
    asm volatile("ldmatrix.sync.aligned.m8n8.x4.trans.shared.b16 {%0,%1,%2,%3}, [%4];" \
        : "=r"((r)[0]), "=r"((r)[1]), "=r"((r)[2]), "=r"((r)[3]) : "r"(a))

#define MMA16816(dd, a, b)                                                     \
    asm volatile("mma.sync.aligned.m16n8k16.row.col.f32.bf16.bf16.f32 "        \
        "{%0,%1,%2,%3}, {%4,%5,%6,%7}, {%8,%9}, {%0,%1,%2,%3};"                \
        : "+f"((dd)[0]), "+f"((dd)[1]), "+f"((dd)[2]), "+f"((dd)[3])           \
        : "r"((a)[0]), "r"((a)[1]), "r"((a)[2]), "r"((a)[3]),                  \
          "r"((b)[0]), "r"((b)[1]))

#define CP_ASYNC16(dst, src)                                                   \
    asm volatile("cp.async.cg.shared.global [%0], [%1], 16;"                   \
        :: "r"(dst), "l"(src))
#define CP_COMMIT() asm volatile("cp.async.commit_group;")
#define CP_WAIT(n)  asm volatile("cp.async.wait_group %0;" :: "n"(n))

// ---------------------------------------------------------------------------
// Kernel 0: W -> W^T hi/lo via smem transpose (coalesced 128B row writes).
// ---------------------------------------------------------------------------
__global__ __launch_bounds__(256) void wconv_kernel(
    const float* __restrict__ Wq, const float* __restrict__ Wk,
    const float* __restrict__ Wv)
{
    __shared__ float tile[64][65];
    const int m  = blockIdx.y;
    const int e0 = blockIdx.x * 64;
    const float* W = (m == 0) ? Wq : (m == 1 ? Wk : Wv);
    const int tid = threadIdx.x;

    #pragma unroll
    for (int it = 0; it < 4; ++it) {
        int e  = (tid >> 4) + it * 16;
        int h4 = (tid & 15) * 4;
        float4 v = *(const float4*)(W + (size_t)(e0 + e) * NH + h4);
        tile[h4 + 0][e] = v.x; tile[h4 + 1][e] = v.y;
        tile[h4 + 2][e] = v.z; tile[h4 + 3][e] = v.w;
    }
    __syncthreads();

    #pragma unroll
    for (int it = 0; it < 4; ++it) {
        int u   = tid + it * 256;
        int arr = u >> 9;
        int rem = u & 511;
        int h   = rem >> 3;
        int gp  = rem & 7;
        uint32_t pk[4];
        #pragma unroll
        for (int j = 0; j < 4; ++j) {
            float f0 = tile[h][gp * 8 + 2 * j];
            float f1 = tile[h][gp * 8 + 2 * j + 1];
            uint32_t hi, lo;
            split2(f0, f1, hi, lo);
            pk[j] = arr ? lo : hi;
        }
        __nv_bfloat16* dst = (arr ? g_WTlo : g_WThi) +
                             ((size_t)(m * NH + h) * NE + e0 + gp * 8);
        *(uint4*)dst = make_uint4(pk[0], pk[1], pk[2], pk[3]);
    }
}

// ---------------------------------------------------------------------------
// Kernel 1: fused QKV projection, mma.sync bf16 split-2, PIPELINED
// (byte-identical to the verified Round-12/14 version).
// ---------------------------------------------------------------------------
#define QSM_AHI 0
#define QSM_ALO 16384
#define QSM_B0  32768
#define QSM_B1  81920
#define QSM_BLO_OFF 24576
#define QSM_BYTES 131072

__global__ __launch_bounds__(512, 1) void qkv_mma_kernel(const float* __restrict__ x)
{
    extern __shared__ char smem[];
    const uint32_t sb = s2u(smem);
    const int tid  = threadIdx.x;
    const int lane = tid & 31;
    const int wid  = tid >> 5;
    const int wm   = wid & 3;
    const int wn   = wid >> 2;
    const int row0 = blockIdx.x * 128;

    float d[2][6][4] = {};

    const int xr = tid >> 2;
    const int xk = (tid & 3) * 16;

    int wsp[6], wrow[6], wq[6];
    uint32_t wdst[6];
    #pragma unroll
    for (int i = 0; i < 6; ++i) {
        int lin = tid + i * 512;
        wsp[i]  = (lin >= 1536) ? 1 : 0;
        int l2  = lin - wsp[i] * 1536;
        wrow[i] = l2 >> 3;
        wq[i]   = l2 & 7;
        wdst[i] = (uint32_t)(wsp[i] * QSM_BLO_OFF + wrow[i] * 128 +
                             ((wq[i] * 16) ^ ((wrow[i] & 7) << 4)));
    }

    float4 xrg[4];
    #pragma unroll
    for (int i = 0; i < 4; ++i)
        xrg[i] = *(const float4*)(x + (size_t)(row0 + xr) * NE + xk + i * 4);
    #pragma unroll
    for (int i = 0; i < 6; ++i) {
        const __nv_bfloat16* src =
            (wsp[i] ? g_WTlo : g_WThi) + ((size_t)wrow[i] * NE + wq[i] * 8);
        CP_ASYNC16(sb + QSM_B0 + wdst[i], src);
    }
    CP_COMMIT();

    #pragma unroll 1
    for (int c = 0; c < 16; ++c) {
        const uint32_t bbase = (c & 1) ? QSM_B1 : QSM_B0;
        __syncthreads();

        #pragma unroll
        for (int i = 0; i < 4; ++i) {
            int k = xk + i * 4;
            uint32_t hi01, lo01, hi23, lo23;
            split2(xrg[i].x, xrg[i].y, hi01, lo01);
            split2(xrg[i].z, xrg[i].w, hi23, lo23);
            uint32_t off = (uint32_t)(xr * 128) + (uint32_t)((k * 2) ^ ((xr & 7) << 4));
            *(uint2*)(smem + QSM_AHI + off) = make_uint2(hi01, hi23);
            *(uint2*)(smem + QSM_ALO + off) = make_uint2(lo01, lo23);
        }

        if (c < 15) {
            const int k0n = (c + 1) * 64;
            const uint32_t nb = (c & 1) ? QSM_B0 : QSM_B1;
            #pragma unroll
            for (int i = 0; i < 6; ++i) {
                const __nv_bfloat16* src =
                    (wsp[i] ? g_WTlo : g_WThi) +
                    ((size_t)wrow[i] * NE + k0n + wq[i] * 8);
                CP_ASYNC16(sb + nb + wdst[i], src);
            }
            CP_COMMIT();
            #pragma unroll
            for (int i = 0; i < 4; ++i)
                xrg[i] = *(const float4*)(x + (size_t)(row0 + xr) * NE + k0n + xk + i * 4);
            CP_WAIT(1);
        } else {
            CP_WAIT(0);
        }
        __syncthreads();

        #pragma unroll
        for (int ks = 0; ks < 4; ++ks) {
            const int kb = ks * 32;
            uint32_t aH[2][4], aL[2][4];
            {
                int lr  = lane & 15;
                int lkb = kb + ((lane >> 4) << 4);
                #pragma unroll
                for (int mf = 0; mf < 2; ++mf) {
                    int r = wm * 32 + mf * 16 + lr;
                    uint32_t a = sb + QSM_AHI + r * 128 + (lkb ^ ((r & 7) << 4));
                    LDSM4(aH[mf], a);
                    LDSM4(aL[mf], a + (QSM_ALO - QSM_AHI));
                }
            }
            uint32_t bH[3][4], bL[3][4];
            {
                int nro = (lane & 7) + ((lane >> 4) << 3);
                int lkb = kb + (((lane >> 3) & 1) << 4);
                #pragma unroll
                for (int p = 0; p < 3; ++p) {
                    int r = wn * 48 + p * 16 + nro;
                    uint32_t a = sb + bbase + r * 128 + (lkb ^ ((r & 7) << 4));
                    LDSM4(bH[p], a);
                    LDSM4(bL[p], a + QSM_BLO_OFF);
                }
            }
            #pragma unroll
            for (int mf = 0; mf < 2; ++mf) {
                #pragma unroll
                for (int nf = 0; nf < 6; ++nf) {
                    uint32_t* bh = &bH[nf >> 1][(nf & 1) * 2];
                    uint32_t* bl = &bL[nf >> 1][(nf & 1) * 2];
                    MMA16816(d[mf][nf], aH[mf], bh);
                    MMA16816(d[mf][nf], aH[mf], bl);
                    MMA16816(d[mf][nf], aL[mf], bh);
                }
            }
        }
    }

    const int g = lane >> 2, t = lane & 3;
    #pragma unroll
    for (int mf = 0; mf < 2; ++mf) {
        int r_lo = row0 + wm * 32 + mf * 16 + g;
        #pragma unroll
        for (int nf = 0; nf < 6; ++nf) {
            int col = wn * 48 + nf * 8 + 2 * t;
            int m = col >> 6, h = col & 63;
            float sc = (m == 0) ? 0.125f : 1.0f;
            __nv_bfloat16* Ohi = (m == 0) ? g_Qhi : (m == 1 ? g_Khi : g_Vhi);
            __nv_bfloat16* Olo = (m == 0) ? g_Qlo : (m == 1 ? g_Klo : g_Vlo);
            uint32_t hi, lo;
            split2(d[mf][nf][0] * sc, d[mf][nf][1] * sc, hi, lo);
            *(uint32_t*)(Ohi + (size_t)r_lo * NH + h) = hi;
            *(uint32_t*)(Olo + (size_t)r_lo * NH + h) = lo;
            split2(d[mf][nf][2] * sc, d[mf][nf][3] * sc, hi, lo);
            *(uint32_t*)(Ohi + (size_t)(r_lo + 8) * NH + h) = hi;
            *(uint32_t*)(Olo + (size_t)(r_lo + 8) * NH + h) = lo;
        }
    }
}

// ---------------------------------------------------------------------------
// Kernel 2: causal flash attention (R14 structure: paired 128-CTA grid,
// 256 thr, 2-product S, no-max softmax, double-buffered KV, 1 barrier/tile).
// CHANGE vs R14: KV moved via cp.async (no register round-trip, no STS
// publish phase, ~32 fewer regs). One group in flight; issue tile jt+1 right
// after the loop-top wait+barrier (its target buffer was last read in
// compute jt-1, fenced by that barrier).
// ---------------------------------------------------------------------------
#define ASM_QHI  0
#define ASM_KV0  8192
#define ASM_KV1  40960
#define ASM_REDL 73728
#define ASM_BYTES 74240
#define MASKV (-1e30f)

__global__ __launch_bounds__(256, 1) void attn_mma_kernel(float* __restrict__ out)
{
    extern __shared__ char sm[];
    const uint32_t sb = s2u(sm);
    float* REDl = (float*)(sm + ASM_REDL);

    const int tid  = threadIdx.x;
    const int lane = tid & 31;
    const int wid  = tid >> 5;
    const int wm   = wid & 3;     // m-slice (16 rows)
    const int ns   = wid >> 2;    // n-side (key cols 0..31 / 32..63)
    const int g    = lane >> 2;
    const int t    = lane & 3;
    const int b    = blockIdx.y;

    const size_t boff = (size_t)b * NT * NH;
    const __nv_bfloat16* kvp[4] = {g_Khi + boff, g_Klo + boff,
                                   g_Vhi + boff, g_Vlo + boff};
    float* Ob = out + boff;

    // Per-thread cp.async slot: 8 x 16B per tile.
    // u = tid + it*256 -> arr (K/V hi/lo), row, 16B group.
    #pragma unroll 1
    for (int qi = 0; qi < 2; ++qi) {
        const int qt   = qi ? (int)blockIdx.x : 31 - (int)blockIdx.x;
        const int row0 = qt * 64;

        __syncthreads();  // previous q-tile's smem readers (Q, Oex) done

        // Q tile (hi only) -> smem: 512 uint4, 2 per thread.
        #pragma unroll
        for (int it = 0; it < 2; ++it) {
            int u = tid + it * 256;
            int r = u >> 3, gp = u & 7;
            const __nv_bfloat16* src =
                g_Qhi + boff + (size_t)(row0 + r) * NH + gp * 8;
            uint4 v = *(const uint4*)src;
            *(uint4*)(sm + ASM_QHI + r * 128 +
                      ((gp * 16) ^ ((r & 7) << 4))) = v;
        }

        // Tile 0 -> buf0 via cp.async.
        #pragma unroll
        for (int it = 0; it < 8; ++it) {
            int u = tid + it * 256;
            int arr = u >> 9, rem = u & 511;
            int r = rem >> 3, gp = rem & 7;
            CP_ASYNC16(sb + ASM_KV0 + arr * 8192 + r * 128 +
                           ((gp * 16) ^ ((r & 7) << 4)),
                       kvp[arr] + (size_t)r * NH + gp * 8);
        }
        CP_COMMIT();

        float Of[8][4] = {};
        float lsum0 = 0.f, lsum1 = 0.f;

        #pragma unroll 1
        for (int jt = 0; jt <= qt; ++jt) {
            const uint32_t ub = sb + ((jt & 1) ? ASM_KV1 : ASM_KV0);

            CP_WAIT(0);        // tile jt arrived
            __syncthreads();   // visible to all; compute jt-1 done everywhere

            // Issue tile jt+1 into the other buffer (overlaps compute jt).
            if (jt < qt) {
                const uint32_t nb = sb + ((jt & 1) ? ASM_KV0 : ASM_KV1);
                #pragma unroll
                for (int it = 0; it < 8; ++it) {
                    int u = tid + it * 256;
                    int arr = u >> 9, rem = u & 511;
                    int r = rem >> 3, gp = rem & 7;
                    CP_ASYNC16(nb + arr * 8192 + r * 128 +
                                   ((gp * 16) ^ ((r & 7) << 4)),
                               kvp[arr] + (size_t)((jt + 1) * 64 + r) * NH + gp * 8);
                }
                CP_COMMIT();
            }

            // ---- S = Q K^T (2 split products: qH*kH + qH*kL) ----
            float S[4][4] = {};
            #pragma unroll
            for (int kf = 0; kf < 4; ++kf) {
                const int kb = kf * 32;
                uint32_t aH[4];
                {
                    int r = wm * 16 + (lane & 15);
                    int lkb = kb + ((lane >> 4) << 4);
                    uint32_t a = sb + ASM_QHI + r * 128 + (lkb ^ ((r & 7) << 4));
                    LDSM4(aH, a);
                }
                uint32_t bKH[2][4], bKL[2][4];
                {
                    int nro = (lane & 7) + ((lane >> 4) << 3);
                    int lkb = kb + (((lane >> 3) & 1) << 4);
                    #pragma unroll
                    for (int p = 0; p < 2; ++p) {
                        int r = ns * 32 + p * 16 + nro;
                        uint32_t a = ub + r * 128 + (lkb ^ ((r & 7) << 4));
                        LDSM4(bKH[p], a);
                        LDSM4(bKL[p], a + 8192);
                    }
                }
                #pragma unroll
                for (int nf = 0; nf < 4; ++nf) {
                    uint32_t* bh = &bKH[nf >> 1][(nf & 1) * 2];
                    uint32_t* bl = &bKL[nf >> 1][(nf & 1) * 2];
                    MMA16816(S[nf], aH, bh);
                    MMA16816(S[nf], aH, bl);
                }
            }

            // ---- mask (diag tile only) + exp (shift-0 softmax) ----
            if (jt == qt) {
                #pragma unroll
                for (int nf = 0; nf < 4; ++nf) {
                    int col = ns * 32 + nf * 8 + 2 * t;
                    int r0r = wm * 16 + g;
                    if (col     > r0r)     S[nf][0] = MASKV;
                    if (col + 1 > r0r)     S[nf][1] = MASKV;
                    if (col     > r0r + 8) S[nf][2] = MASKV;
                    if (col + 1 > r0r + 8) S[nf][3] = MASKV;
                }
            }
            #pragma unroll
            for (int nf = 0; nf < 4; ++nf) {
                S[nf][0] = __expf(S[nf][0]); lsum0 += S[nf][0];
                S[nf][1] = __expf(S[nf][1]); lsum0 += S[nf][1];
                S[nf][2] = __expf(S[nf][2]); lsum1 += S[nf][2];
                S[nf][3] = __expf(S[nf][3]); lsum1 += S[nf][3];
            }

            // ---- pack P into A-fragments (register-only) ----
            uint32_t pH[2][4], pL[2][4];
            #pragma unroll
            for (int kk = 0; kk < 2; ++kk) {
                split2(S[2 * kk][0],     S[2 * kk][1],     pH[kk][0], pL[kk][0]);
                split2(S[2 * kk][2],     S[2 * kk][3],     pH[kk][1], pL[kk][1]);
                split2(S[2 * kk + 1][0], S[2 * kk + 1][1], pH[kk][2], pL[kk][2]);
                split2(S[2 * kk + 1][2], S[2 * kk + 1][3], pH[kk][3], pL[kk][3]);
            }

            // ---- O += P V over this warp's 32 keys ----
            #pragma unroll
            for (int kk = 0; kk < 2; ++kk) {
                int jrow = ns * 32 + kk * 16 + (lane & 7) + ((lane >> 3) & 1) * 8;
                #pragma unroll
                for (int hp = 0; hp < 4; ++hp) {
                    int hbyte = hp * 32 + ((lane >> 4) << 4);
                    uint32_t a = ub + 16384 + jrow * 128 +
                                 (hbyte ^ ((jrow & 7) << 4));
                    uint32_t vH[4], vL[4];
                    LDSM4T(vH, a);
                    LDSM4T(vL, a + 8192);
                    #pragma unroll
                    for (int e = 0; e < 2; ++e) {
                        int hf = 2 * hp + e;
                        uint32_t* bh = &vH[e * 2];
                        uint32_t* bl = &vL[e * 2];
                        MMA16816(Of[hf], pH[kk], bh);
                        MMA16816(Of[hf], pH[kk], bl);
                        MMA16816(Of[hf], pL[kk], bh);
                    }
                }
            }
        }

        // ---- reduce l within quad (once per q-tile) ----
        lsum0 += __shfl_xor_sync(0xffffffffu, lsum0, 1);
        lsum0 += __shfl_xor_sync(0xffffffffu, lsum0, 2);
        lsum1 += __shfl_xor_sync(0xffffffffu, lsum1, 1);
        lsum1 += __shfl_xor_sync(0xffffffffu, lsum1, 2);

        // ---- merge the two n-side accumulators, normalize, store ----
        __syncthreads();  // all compute (incl. reads of KV0) done
        if (ns == 1) {
            float* Oex = (float*)(sm + ASM_KV0);
            #pragma unroll
            for (int hf = 0; hf < 8; ++hf)
                *(float4*)&Oex[((wm * 32 + lane) * 32) + hf * 4] =
                    make_float4(Of[hf][0], Of[hf][1], Of[hf][2], Of[hf][3]);
            if (t == 0) {
                REDl[wm * 16 + g]     = lsum0;
                REDl[wm * 16 + 8 + g] = lsum1;
            }
        }
        __syncthreads();
        if (ns == 0) {
            const float* Oex = (const float*)(sm + ASM_KV0);
            float lt0 = lsum0 + REDl[wm * 16 + g];
            float lt1 = lsum1 + REDl[wm * 16 + 8 + g];
            float inv0 = 1.0f / lt0;
            float inv1 = 1.0f / lt1;
            int r_g = row0 + wm * 16 + g;
            #pragma unroll
            for (int hf = 0; hf < 8; ++hf) {
                float4 ox = *(const float4*)&Oex[((wm * 32 + lane) * 32) + hf * 4];
                int h = hf * 8 + 2 * t;
                *(float2*)(Ob + (size_t)r_g * NH + h) =
                    make_float2((Of[hf][0] + ox.x) * inv0, (Of[hf][1] + ox.y) * inv0);
                *(float2*)(Ob + (size_t)(r_g + 8) * NH + h) =
                    make_float2((Of[hf][2] + ox.z) * inv1, (Of[hf][3] + ox.w) * inv1);
            }
        }
    }
}

extern "C" void kernel_launch(void* const* d_in, const int* in_sizes, int n_in,
                              void* d_out, int out_size)
{
    const float* x  = (const float*)d_in[0];
    const float* Wq = (const float*)d_in[1];
    const float* Wk = (const float*)d_in[2];
    const float* Wv = (const float*)d_in[3];
    float* out = (float*)d_out;

    (void)cudaFuncSetAttribute(qkv_mma_kernel,
                               cudaFuncAttributeMaxDynamicSharedMemorySize, QSM_BYTES);
    (void)cudaFuncSetAttribute(attn_mma_kernel,
                               cudaFuncAttributeMaxDynamicSharedMemorySize, ASM_BYTES);

    wconv_kernel<<<dim3(16, 3), 256>>>(Wq, Wk, Wv);
    qkv_mma_kernel<<<128, 512, QSM_BYTES>>>(x);
    attn_mma_kernel<<<dim3(16, 8), 256, ASM_BYTES>>>(out);
}